// round 5
// baseline (speedup 1.0000x reference)
#include <cuda_runtime.h>
#include <math.h>
#include <stdint.h>

#define T 1024
#define C 128
#define NB 16
#define LUP 523776          // T*(T-1)/2
#define NOUT 2046           // LUP / 256
#define LEAK 0.2f

// ---------------------------------------------------------------------------
// Device globals (scratch)
// ---------------------------------------------------------------------------
__device__ float g_up[(size_t)NB * LUP];   // packed upper-triangle distances
__device__ float g_xx[NB * T];             // row squared norms

// ---------------------------------------------------------------------------
// Helpers
// ---------------------------------------------------------------------------
__device__ __forceinline__ uint32_t to_tf32(float f) {
    uint32_t r;
    asm("cvt.rna.tf32.f32 %0, %1;" : "=r"(r) : "f"(f));
    return r;
}

__device__ __forceinline__ void mma_tf32(float* d, const uint32_t* a, const uint32_t* b) {
    asm volatile(
        "mma.sync.aligned.m16n8k8.row.col.f32.tf32.tf32.f32 "
        "{%0,%1,%2,%3}, {%4,%5,%6,%7}, {%8,%9}, {%0,%1,%2,%3};"
        : "+f"(d[0]), "+f"(d[1]), "+f"(d[2]), "+f"(d[3])
        : "r"(a[0]), "r"(a[1]), "r"(a[2]), "r"(a[3]),
          "r"(b[0]), "r"(b[1]));
}

__device__ __forceinline__ float lrelu(float v) {
    return fmaxf(v, LEAK * v);
}

// ---------------------------------------------------------------------------
// Kernel 1: xx[b][i] = sum_c x[b][i][c]^2.  One warp per row.
// ---------------------------------------------------------------------------
__global__ __launch_bounds__(256) void xx_kernel(const float* __restrict__ x) {
    int warp = (blockIdx.x * 256 + threadIdx.x) >> 5;
    int lane = threadIdx.x & 31;
    if (warp >= NB * T) return;
    const float4* row = (const float4*)(x + (size_t)warp * C);
    float4 v = row[lane];
    float s = v.x * v.x + v.y * v.y + v.z * v.z + v.w * v.w;
    #pragma unroll
    for (int o = 16; o; o >>= 1) s += __shfl_xor_sync(0xffffffffu, s, o);
    if (lane == 0) g_xx[warp] = s;
}

// ---------------------------------------------------------------------------
// Kernel 2: tf32 mma.sync Gram tiles -> packed sqrt distances.
// (verbatim from round-3 passing build)
// ---------------------------------------------------------------------------
#define AS_STRIDE 132
#define AS_BYTES  (128 * AS_STRIDE * 4)       // 67584
#define DIST_SMEM (2 * AS_BYTES)              // 135168

__global__ __launch_bounds__(256) void dist_kernel(const float* __restrict__ x) {
    extern __shared__ __align__(16) unsigned char sm[];
    uint32_t* As = (uint32_t*)sm;
    uint32_t* Bs = (uint32_t*)(sm + AS_BYTES);

    int tid = threadIdx.x;
    int wid = tid >> 5;
    int lane = tid & 31;
    int grp = lane >> 2;        // 0..7
    int tg  = lane & 3;         // 0..3

    int b = blockIdx.y;
    int t = blockIdx.x;
    int ti = 0, rem = t;
    while (rem >= 8 - ti) { rem -= 8 - ti; ++ti; }
    int tj = ti + rem;
    int i0 = ti * 128, j0 = tj * 128;

    const float* xb = x + (size_t)b * T * C;

    #pragma unroll
    for (int it = 0; it < 16; ++it) {
        int f4 = it * 256 + tid;
        int row = f4 >> 5, c4 = f4 & 31;
        float4 va = *(const float4*)(xb + (size_t)(i0 + row) * C + c4 * 4);
        uint4 ta = make_uint4(to_tf32(va.x), to_tf32(va.y), to_tf32(va.z), to_tf32(va.w));
        *(uint4*)&As[row * AS_STRIDE + c4 * 4] = ta;
        float4 vb = *(const float4*)(xb + (size_t)(j0 + row) * C + c4 * 4);
        uint4 tb = make_uint4(to_tf32(vb.x), to_tf32(vb.y), to_tf32(vb.z), to_tf32(vb.w));
        *(uint4*)&Bs[row * AS_STRIDE + c4 * 4] = tb;
    }
    __syncthreads();

    int warp_m = (wid >> 2) * 64;
    int warp_n = (wid & 3) * 32;

    float acc[4][4][4];
    #pragma unroll
    for (int e = 0; e < 4; ++e)
        #pragma unroll
        for (int f = 0; f < 4; ++f)
            #pragma unroll
            for (int q = 0; q < 4; ++q) acc[e][f][q] = 0.0f;

    int abase = (warp_m + grp) * AS_STRIDE + tg;
    int bbase = (warp_n + grp) * AS_STRIDE + tg;

    #pragma unroll 2
    for (int kb = 0; kb < 128; kb += 8) {
        uint32_t a[4][4], bf[4][2];
        #pragma unroll
        for (int e = 0; e < 4; ++e) {
            int r = abase + 16 * e * AS_STRIDE + kb;
            a[e][0] = As[r];
            a[e][1] = As[r + 8 * AS_STRIDE];
            a[e][2] = As[r + 4];
            a[e][3] = As[r + 8 * AS_STRIDE + 4];
        }
        #pragma unroll
        for (int f = 0; f < 4; ++f) {
            int r = bbase + 8 * f * AS_STRIDE + kb;
            bf[f][0] = Bs[r];
            bf[f][1] = Bs[r + 4];
        }
        #pragma unroll
        for (int e = 0; e < 4; ++e)
            #pragma unroll
            for (int f = 0; f < 4; ++f)
                mma_tf32(acc[e][f], a[e], bf[f]);
    }

    float xi[4][2], xj[4][2];
    #pragma unroll
    for (int e = 0; e < 4; ++e) {
        int il = warp_m + 16 * e + grp;
        xi[e][0] = g_xx[b * T + i0 + il];
        xi[e][1] = g_xx[b * T + i0 + il + 8];
    }
    #pragma unroll
    for (int f = 0; f < 4; ++f) {
        int jl = warp_n + 8 * f + 2 * tg;
        xj[f][0] = g_xx[b * T + j0 + jl];
        xj[f][1] = g_xx[b * T + j0 + jl + 1];
    }

    __syncthreads();
    float* S = (float*)sm;   // 128 x stride-129 staging

    #pragma unroll
    for (int e = 0; e < 4; ++e) {
        int il = warp_m + 16 * e + grp;
        #pragma unroll
        for (int f = 0; f < 4; ++f) {
            int jl = warp_n + 8 * f + 2 * tg;
            float d00 = fmaf(-2.0f, acc[e][f][0], xi[e][0] + xj[f][0]);
            float d01 = fmaf(-2.0f, acc[e][f][1], xi[e][0] + xj[f][1]);
            float d10 = fmaf(-2.0f, acc[e][f][2], xi[e][1] + xj[f][0]);
            float d11 = fmaf(-2.0f, acc[e][f][3], xi[e][1] + xj[f][1]);
            S[il * 129 + jl]           = sqrtf(fmaxf(d00, 0.0f));
            S[il * 129 + jl + 1]       = sqrtf(fmaxf(d01, 0.0f));
            S[(il + 8) * 129 + jl]     = sqrtf(fmaxf(d10, 0.0f));
            S[(il + 8) * 129 + jl + 1] = sqrtf(fmaxf(d11, 0.0f));
        }
    }
    __syncthreads();

    {
        long bbase2 = (long)b * LUP;
        #pragma unroll
        for (int q = tid; q < 128 * 128; q += 256) {
            int m = q >> 7, jj = q & 127;
            int i2 = i0 + m, j2 = j0 + jj;
            if (j2 > i2) {
                long ro = (long)i2 * (2 * T - 1 - i2) / 2 - i2 - 1;
                g_up[bbase2 + ro + j2] = S[m * 129 + jj];
            }
        }
    }
}

// ---------------------------------------------------------------------------
// Kernel 3 (v2): fused 8-layer conv stack, LDS-optimized.
// 31 final outputs per block (2046 = 66 * 31) -> 7936 inputs.
// Fused L0+L1 in registers; layers use float4 LDS/STS, channel-inner layout;
// weights read via broadcast LDS with immediate offsets (fully unrolled).
// ---------------------------------------------------------------------------
#define CONV_NPOS1 1984                 // L1 positions per block
#define CONV_IN    7936                 // inputs per block
#define OFF_W   0
#define OFF_B0  1024
#define OFF_B1  (1024 + CONV_IN)
#define CONV_SMEM ((1024 + CONV_IN + 8 * CONV_NPOS1) * 4)   // 99328 B

// one generic 8ch->8ch layer step for position p (inputs 2p,2p+1)
__device__ __forceinline__ void conv_layer_pos(
    const float* __restrict__ W, const float* __restrict__ B,
    const float* __restrict__ src, float* __restrict__ dst, int p, bool act)
{
    float4 a0 = *(const float4*)&src[16 * p];
    float4 a1 = *(const float4*)&src[16 * p + 4];
    float4 a2 = *(const float4*)&src[16 * p + 8];
    float4 a3 = *(const float4*)&src[16 * p + 12];
    float in0[8] = {a0.x, a0.y, a0.z, a0.w, a1.x, a1.y, a1.z, a1.w};
    float in1[8] = {a2.x, a2.y, a2.z, a2.w, a3.x, a3.y, a3.z, a3.w};
    float o[8];
    #pragma unroll
    for (int c = 0; c < 8; ++c) {
        float acc = B[c];
        #pragma unroll
        for (int ci = 0; ci < 8; ++ci) {
            acc = fmaf(W[c * 16 + 2 * ci],     in0[ci], acc);
            acc = fmaf(W[c * 16 + 2 * ci + 1], in1[ci], acc);
        }
        o[c] = act ? lrelu(acc) : acc;
    }
    *(float4*)&dst[8 * p]     = make_float4(o[0], o[1], o[2], o[3]);
    *(float4*)&dst[8 * p + 4] = make_float4(o[4], o[5], o[6], o[7]);
}

__global__ __launch_bounds__(256, 2) void conv_kernel(
    const float* __restrict__ w0, const float* __restrict__ b0,
    const float* __restrict__ w1, const float* __restrict__ b1,
    const float* __restrict__ w2, const float* __restrict__ b2,
    const float* __restrict__ w3, const float* __restrict__ b3,
    const float* __restrict__ w4, const float* __restrict__ b4,
    const float* __restrict__ w5, const float* __restrict__ b5,
    const float* __restrict__ w6, const float* __restrict__ b6,
    const float* __restrict__ w7, const float* __restrict__ b7,
    float* __restrict__ out)
{
    extern __shared__ __align__(16) float cs[];
    float* wgt  = cs + OFF_W;
    float* buf0 = cs + OFF_B0;
    float* buf1 = cs + OFF_B1;

    int tid = threadIdx.x;
    int b   = blockIdx.y;
    int blk = blockIdx.x;        // 0..65

    // ---- stage weights ----
    if (tid < 128) {
        wgt[ 24 + tid] = w1[tid];
        wgt[152 + tid] = w2[tid];
        wgt[280 + tid] = w3[tid];
        wgt[408 + tid] = w4[tid];
        wgt[536 + tid] = w5[tid];
        wgt[664 + tid] = w6[tid];
    } else {
        int u = tid - 128;
        if (u < 16)       wgt[u]            = w0[u];
        else if (u < 24)  wgt[u]            = b0[u - 16];
        else if (u < 32)  wgt[792 + (u-24)] = b1[u-24];
        else if (u < 40)  wgt[800 + (u-32)] = b2[u-32];
        else if (u < 48)  wgt[808 + (u-40)] = b3[u-40];
        else if (u < 56)  wgt[816 + (u-48)] = b4[u-48];
        else if (u < 64)  wgt[824 + (u-56)] = b5[u-56];
        else if (u < 72)  wgt[832 + (u-64)] = b6[u-64];
        else if (u < 88)  wgt[840 + (u-72)] = w7[u-72];
        else if (u == 88) wgt[856]          = b7[0];
    }

    // ---- load 7936 contiguous packed distances (float4, coalesced) ----
    {
        const float4* src = (const float4*)(g_up + (size_t)b * LUP + (size_t)blk * CONV_IN);
        float4* dst = (float4*)buf0;
        #pragma unroll
        for (int q = tid; q < CONV_IN / 4; q += 256) dst[q] = src[q];
    }
    __syncthreads();

    // ---- fused L0+L1: inputs 4p..4p+3 -> L1 position p (8ch) ----
    {
        const float* W1 = wgt + 24;
        const float* B1 = wgt + 792;
        for (int p = tid; p < CONV_NPOS1; p += 256) {
            float4 u = *(const float4*)&buf0[4 * p];
            float v0[8], v1[8];
            #pragma unroll
            for (int c = 0; c < 8; ++c) {
                float bc = wgt[16 + c];
                float va = fmaf(wgt[2*c], u.x, fmaf(wgt[2*c + 1], u.y, bc));
                float vb = fmaf(wgt[2*c], u.z, fmaf(wgt[2*c + 1], u.w, bc));
                v0[c] = lrelu(va);
                v1[c] = lrelu(vb);
            }
            float o[8];
            #pragma unroll
            for (int c = 0; c < 8; ++c) {
                float acc = B1[c];
                #pragma unroll
                for (int ci = 0; ci < 8; ++ci) {
                    acc = fmaf(W1[c * 16 + 2 * ci],     v0[ci], acc);
                    acc = fmaf(W1[c * 16 + 2 * ci + 1], v1[ci], acc);
                }
                o[c] = lrelu(acc);
            }
            *(float4*)&buf1[8 * p]     = make_float4(o[0], o[1], o[2], o[3]);
            *(float4*)&buf1[8 * p + 4] = make_float4(o[4], o[5], o[6], o[7]);
        }
    }
    __syncthreads();

    // ---- L2: buf1 -> buf0 (992 pos) ----
    for (int p = tid; p < 992; p += 256)
        conv_layer_pos(wgt + 152, wgt + 800, buf1, buf0, p, true);
    __syncthreads();

    // ---- L3: buf0 -> buf1 (496) ----
    for (int p = tid; p < 496; p += 256)
        conv_layer_pos(wgt + 280, wgt + 808, buf0, buf1, p, true);
    __syncthreads();

    // ---- L4: buf1 -> buf0 (248) ----
    if (tid < 248)
        conv_layer_pos(wgt + 408, wgt + 816, buf1, buf0, tid, true);
    __syncthreads();

    // ---- L5: buf0 -> buf1 (124) ----
    if (tid < 124)
        conv_layer_pos(wgt + 536, wgt + 824, buf0, buf1, tid, true);
    __syncthreads();

    // ---- L6: buf1 -> buf0 (62) ----
    if (tid < 62)
        conv_layer_pos(wgt + 664, wgt + 832, buf1, buf0, tid, true);
    __syncthreads();

    // ---- L7: buf0 -> out (31, single channel, no activation) ----
    if (tid < 31) {
        int p = tid;
        const float* s0 = buf0 + 16 * p;
        float acc = wgt[856];
        #pragma unroll
        for (int ci = 0; ci < 8; ++ci) {
            acc = fmaf(wgt[840 + 2*ci], s0[ci],     acc);
            acc = fmaf(wgt[841 + 2*ci], s0[8 + ci], acc);
        }
        out[b * NOUT + blk * 31 + p] = acc;
    }
}

// ---------------------------------------------------------------------------
extern "C" void kernel_launch(void* const* d_in, const int* in_sizes, int n_in,
                              void* d_out, int out_size) {
    const float* x = (const float*)d_in[0];
    const float* w[8];
    const float* bb[8];
    for (int i = 0; i < 8; ++i) {
        w[i]  = (const float*)d_in[1 + 2 * i];
        bb[i] = (const float*)d_in[2 + 2 * i];
    }
    float* out = (float*)d_out;

    cudaFuncSetAttribute(dist_kernel,
                         cudaFuncAttributeMaxDynamicSharedMemorySize, DIST_SMEM);
    cudaFuncSetAttribute(conv_kernel,
                         cudaFuncAttributeMaxDynamicSharedMemorySize, CONV_SMEM);

    xx_kernel<<<(NB * T) / 8, 256>>>(x);
    dist_kernel<<<dim3(36, NB), 256, DIST_SMEM>>>(x);
    conv_kernel<<<dim3(66, NB), 256, CONV_SMEM>>>(
        w[0], bb[0], w[1], bb[1], w[2], bb[2], w[3], bb[3],
        w[4], bb[4], w[5], bb[5], w[6], bb[6], w[7], bb[7], out);
}